// round 12
// baseline (speedup 1.0000x reference)
#include <cuda_runtime.h>
#include <cuda_bf16.h>
#include <cuda_fp16.h>
#include <math.h>
#include <stdint.h>

#define T_SEQ  2048
#define DMODEL 1024
#define NHEADS 16
#define HDIM   64
#define KDIM   1024
#define BK     64
#define NSTAGES (KDIM / BK)      // 16
#define NPIPE  3

// ---------------------------------------------------------------------------
// Scratch (static device globals — no allocation allowed in kernel_launch)
// ---------------------------------------------------------------------------
__device__ float g_q[T_SEQ * DMODEL];
__device__ float g_k[T_SEQ * DMODEL];
__device__ float g_v[T_SEQ * DMODEL];
__device__ __align__(16) __half g_x16[T_SEQ * DMODEL];
__device__ __align__(16) __half g_y16[T_SEQ * DMODEL];
__device__ __align__(16) __half g_Wqkv16[3 * DMODEL * DMODEL];
__device__ __align__(16) __half g_Wp16[DMODEL * DMODEL];
// fp16 q/k/v for attention (q pre-scaled by 0.125*log2e)
__device__ __align__(16) __half g_q16[T_SEQ * DMODEL];
__device__ __align__(16) __half g_k16[T_SEQ * DMODEL];
__device__ __align__(16) __half g_v16[T_SEQ * DMODEL];
// split-K attention partials (uniformly scaled by 2^-12; cancels in combine)
__device__ __align__(16) float g_part[2 * T_SEQ * DMODEL];
__device__ float g_l[2 * T_SEQ * NHEADS];   // [z][t][h] row sums

// ---------------------------------------------------------------------------
__device__ __forceinline__ uint32_t smem_u32(const void* p) {
    uint32_t a;
    asm("{ .reg .u64 t; cvta.to.shared.u64 t, %1; cvt.u32.u64 %0, t; }"
        : "=r"(a) : "l"(p));
    return a;
}

__device__ __forceinline__ void ldsm_x4(uint32_t* r, uint32_t addr) {
    asm volatile("ldmatrix.sync.aligned.m8n8.x4.shared.b16 {%0,%1,%2,%3}, [%4];"
                 : "=r"(r[0]), "=r"(r[1]), "=r"(r[2]), "=r"(r[3]) : "r"(addr));
}

__device__ __forceinline__ void ldsm_x4_t(uint32_t* r, uint32_t addr) {
    asm volatile("ldmatrix.sync.aligned.m8n8.x4.trans.shared.b16 {%0,%1,%2,%3}, [%4];"
                 : "=r"(r[0]), "=r"(r[1]), "=r"(r[2]), "=r"(r[3]) : "r"(addr));
}

// fp16 MMA, fp32 accumulate
__device__ __forceinline__ void mma16816h(float* d, const uint32_t* a,
                                          const uint32_t* b) {
    asm volatile(
        "mma.sync.aligned.m16n8k16.row.col.f32.f16.f16.f32 "
        "{%0,%1,%2,%3}, {%4,%5,%6,%7}, {%8,%9}, {%0,%1,%2,%3};"
        : "+f"(d[0]), "+f"(d[1]), "+f"(d[2]), "+f"(d[3])
        : "r"(a[0]), "r"(a[1]), "r"(a[2]), "r"(a[3]), "r"(b[0]), "r"(b[1]));
}

__device__ __forceinline__ uint32_t pack_half2(float lo, float hi) {
    uint32_t r;
    asm("cvt.rn.f16x2.f32 %0, %1, %2;" : "=r"(r) : "f"(hi), "f"(lo));
    return r;
}

__device__ __forceinline__ float ex2(float x) {
    float r;
    asm("ex2.approx.f32 %0, %1;" : "=f"(r) : "f"(x));
    return r;
}

__device__ __forceinline__ void cp_async16(uint32_t dst, const void* src) {
    asm volatile("cp.async.cg.shared.global [%0], [%1], 16;"
                 :: "r"(dst), "l"(src));
}
#define CP_COMMIT() asm volatile("cp.async.commit_group;" ::: "memory")
#define CP_WAIT(n)  asm volatile("cp.async.wait_group %0;" :: "n"(n) : "memory")

// ---------------------------------------------------------------------------
// fp32 -> fp16 conversion: y selects among {x, Wq, Wk, Wv, Wp}
// ---------------------------------------------------------------------------
extern "C" __global__ void pack16(const float* __restrict__ x,
                                  const float* __restrict__ wq,
                                  const float* __restrict__ wk,
                                  const float* __restrict__ wv,
                                  const float* __restrict__ wp)
{
    const int y = blockIdx.y;
    const float* s;
    __half* d;
    int n4;
    if (y == 0)      { s = x;  d = g_x16;                          n4 = T_SEQ * DMODEL / 4; }
    else if (y == 1) { s = wq; d = g_Wqkv16;                       n4 = DMODEL * DMODEL / 4; }
    else if (y == 2) { s = wk; d = g_Wqkv16 + DMODEL * DMODEL;     n4 = DMODEL * DMODEL / 4; }
    else if (y == 3) { s = wv; d = g_Wqkv16 + 2 * DMODEL * DMODEL; n4 = DMODEL * DMODEL / 4; }
    else             { s = wp; d = g_Wp16;                         n4 = DMODEL * DMODEL / 4; }

    for (int i = blockIdx.x * blockDim.x + threadIdx.x; i < n4;
         i += gridDim.x * blockDim.x) {
        float4 v = ((const float4*)s)[i];
        uint2 o;
        o.x = pack_half2(v.x, v.y);
        o.y = pack_half2(v.z, v.w);
        ((uint2*)d)[i] = o;
    }
}

// ---------------------------------------------------------------------------
// mma.sync fp16 GEMM, cp.async 3-stage pipeline, ONE sync per stage.
// The top sync at stage s orders all warps past their stage s-1 reads of
// buffer (s+2)%3, making the subsequent issue into it safe.
// ---------------------------------------------------------------------------
#define GEMM_SMEM_BYTES (NPIPE * 32768)

extern "C" __global__ void __launch_bounds__(256, 2)
gemm_f16(const __half* __restrict__ A,
         const __half* __restrict__ B,
         float* __restrict__ C0, float* __restrict__ C1,
         float* __restrict__ C2)
{
    extern __shared__ __align__(1024) char smem[];
    const uint32_t sbase = smem_u32(smem);

    const int tid  = threadIdx.x;
    const int wid  = tid >> 5;
    const int lane = tid & 31;
    const int n0 = blockIdx.x * 128;
    const int m0 = blockIdx.y * 128;
    const int wm = (wid >> 2) * 64;
    const int wn = (wid & 3) * 32;

    const int lrow = tid >> 3;
    const int lq   = tid & 7;
    const __half* Ag = A + (size_t)(m0 + lrow) * KDIM + lq * 8;
    const __half* Bg = B + (size_t)(n0 + lrow) * KDIM + lq * 8;
    const uint32_t st_off = lrow * 128 + ((lq ^ (lrow & 7)) << 4);

    uint32_t aoff[4][4], boff[4][2];
    #pragma unroll
    for (int ks = 0; ks < 4; ks++) {
        #pragma unroll
        for (int mf = 0; mf < 4; mf++) {
            int row = wm + 16 * mf + ((lane >> 3) & 1) * 8 + (lane & 7);
            int ch  = 2 * ks + (lane >> 4);
            aoff[ks][mf] = row * 128 + ((ch ^ (row & 7)) << 4);
        }
        #pragma unroll
        for (int np = 0; np < 2; np++) {
            int row = wn + 16 * np + ((lane >> 4) << 3) + (lane & 7);
            int ch  = 2 * ks + ((lane >> 3) & 1);
            boff[ks][np] = row * 128 + ((ch ^ (row & 7)) << 4);
        }
    }

    float acc[4][4][4];
    #pragma unroll
    for (int i = 0; i < 4; i++)
        #pragma unroll
        for (int j = 0; j < 4; j++)
            #pragma unroll
            for (int r = 0; r < 4; r++) acc[i][j][r] = 0.f;

    auto issue = [&](int s) {
        const uint32_t dst = sbase + (s % NPIPE) * 32768 + st_off;
        const size_t ko = (size_t)s * BK;
        #pragma unroll
        for (int j = 0; j < 4; j++) {
            cp_async16(dst + j * 4096,         Ag + (size_t)32 * j * KDIM + ko);
            cp_async16(dst + 16384 + j * 4096, Bg + (size_t)32 * j * KDIM + ko);
        }
        CP_COMMIT();
    };

    issue(0);
    issue(1);

    for (int s = 0; s < NSTAGES; s++) {
        if (s + 1 < NSTAGES) { CP_WAIT(1); } else { CP_WAIT(0); }
        __syncthreads();
        if (s + 2 < NSTAGES) issue(s + 2);

        const uint32_t ab32 = sbase + (s % NPIPE) * 32768;
        const uint32_t bb32 = ab32 + 16384;
        #pragma unroll
        for (int ks = 0; ks < 4; ks++) {
            uint32_t af[4][4], bf[2][4];
            #pragma unroll
            for (int mf = 0; mf < 4; mf++)
                ldsm_x4(af[mf], ab32 + aoff[ks][mf]);
            #pragma unroll
            for (int np = 0; np < 2; np++)
                ldsm_x4(bf[np], bb32 + boff[ks][np]);
            #pragma unroll
            for (int mf = 0; mf < 4; mf++)
                #pragma unroll
                for (int nf = 0; nf < 4; nf++)
                    mma16816h(acc[mf][nf], af[mf], &bf[nf >> 1][(nf & 1) * 2]);
        }
    }

    const int sel = n0 >> 10;
    float* __restrict__ C = (sel == 0) ? C0 : (sel == 1) ? C1 : C2;
    const int nl = n0 & 1023;
    const int gr = lane >> 2;
    const int gc = (lane & 3) * 2;
    #pragma unroll
    for (int mf = 0; mf < 4; mf++)
        #pragma unroll
        for (int nf = 0; nf < 4; nf++) {
            const int row = m0 + wm + 16 * mf + gr;
            const int col = nl + wn + 8 * nf + gc;
            *(float2*)&C[(size_t)row * DMODEL + col] =
                make_float2(acc[mf][nf][0], acc[mf][nf][1]);
            *(float2*)&C[(size_t)(row + 8) * DMODEL + col] =
                make_float2(acc[mf][nf][2], acc[mf][nf][3]);
        }
}

// ---------------------------------------------------------------------------
// Fused post: one warp per (t,h). Lane j owns dims j and j+32.
// q is pre-scaled by 0.125 * log2(e) so attention works in exp2 domain.
// ---------------------------------------------------------------------------
extern "C" __global__ void __launch_bounds__(256)
qkv_post(const float* __restrict__ vi, const float* __restrict__ lambdas)
{
    const int u = blockIdx.x * 8 + (threadIdx.x >> 5);   // unit = t*16+h
    const int j = threadIdx.x & 31;
    const int t = u >> 4;
    const int h = u & 15;
    const int base = t * DMODEL + h * HDIM;
    const int i0 = base + j;
    const int i1 = base + j + 32;

    const float l0 = lambdas[0], l1 = lambdas[1];
    {
        float v0 = fmaf(l0, g_v[i0], l1 * vi[i0]);
        float v1 = fmaf(l0, g_v[i1], l1 * vi[i1]);
        g_v16[i0] = __float2half(v0);
        g_v16[i1] = __float2half(v1);
    }

    float q0 = g_q[i0], q1 = g_q[i1];
    float k0 = g_k[i0], k1 = g_k[i1];
    float qs = q0 * q0 + q1 * q1;
    float ks = k0 * k0 + k1 * k1;
    #pragma unroll
    for (int o = 16; o > 0; o >>= 1) {
        qs += __shfl_xor_sync(0xffffffffu, qs, o);
        ks += __shfl_xor_sync(0xffffffffu, ks, o);
    }
    const float eps = 1.1920929e-7f;
    const float rq = rsqrtf(qs * (1.f / 64.f) + eps);
    const float rk = rsqrtf(ks * (1.f / 64.f) + eps);
    q0 *= rq; q1 *= rq; k0 *= rk; k1 *= rk;

    float c = 1.f, s = 0.f;
    if (j < 16) {
        float invf = exp2f(-10.0f * (float)j * (1.0f / 15.0f));
        sincosf((float)t * invf, &s, &c);
    }
    const float QSC = 0.125f * 1.44269504f;   // 1/sqrt(hd) * log2(e)
    float qa = (q0 * c + q1 * s) * QSC;
    float qb = (q1 * c - q0 * s) * QSC;
    float ka =  k0 * c + k1 * s;
    float kb =  k1 * c - k0 * s;

    g_q16[i0] = __float2half(qa);
    g_q16[i1] = __float2half(qb);
    g_k16[i0] = __float2half(ka);
    g_k16[i1] = __float2half(kb);
}

// ---------------------------------------------------------------------------
// Split-K fp16 flash attention, causal, exp2 domain, fixed softmax max (12),
// 3-deep KV ring with ONE sync per tile. Q staged through ring slot 2.
// ---------------------------------------------------------------------------
#define SW(row, q) ((row) * 128 + (((q) ^ ((row) & 7)) << 4))
#define FLASH_SMEM_BYTES (49152)
#define MAXLOG 12.0f

extern "C" __global__ void __launch_bounds__(256, 2)
flash_mma()
{
    extern __shared__ __align__(1024) char smd[];
    const uint32_t sb = smem_u32(smd);

    const int qt   = (int)gridDim.x - 1 - (int)blockIdx.x;  // heavy first
    const int h    = blockIdx.y;
    const int z    = blockIdx.z;
    const int tid  = threadIdx.x;
    const int lane = tid & 31;
    const int wq   = tid >> 5;
    const int q0   = qt * 128;
    const int ktbeg = z ? (qt + 1) : 0;
    const int ktend = z ? (2 * qt + 1) : qt;   // inclusive
    const size_t hcol = (size_t)h * HDIM;

    const int krow = tid >> 2;            // 0..63
    const int kq2  = (tid & 3) * 2;       // 0,2,4,6
    auto issue_kv = [&](int kt, int buf) {
        const uint32_t dst = sb + buf * 16384;
        const size_t gb = (size_t)(kt * 64 + krow) * DMODEL + hcol + kq2 * 8;
        #pragma unroll
        for (int j = 0; j < 2; j++) {
            const uint32_t so = SW(krow, kq2 + j);
            const size_t go = gb + (size_t)j * 8;
            cp_async16(dst + so,        g_k16 + go);
            cp_async16(dst + 8192 + so, g_v16 + go);
        }
        CP_COMMIT();
    };

    // prologue: kv[ktbeg] -> ring0 ; Q -> ring2 (reclaimed after frag load)
    issue_kv(ktbeg, 0);
    {
        const int qrow = tid >> 1;
        const int qqb  = (tid & 1) * 4;
        const uint32_t dst = sb + 32768;
        const size_t gb = (size_t)(q0 + qrow) * DMODEL + hcol + qqb * 8;
        #pragma unroll
        for (int j = 0; j < 4; j++)
            cp_async16(dst + SW(qrow, qqb + j), g_q16 + gb + (size_t)j * 8);
        CP_COMMIT();
    }
    CP_WAIT(0);
    __syncthreads();

    uint32_t qf[4][4];
    #pragma unroll
    for (int ks = 0; ks < 4; ks++) {
        int row = wq * 16 + ((lane >> 3) & 1) * 8 + (lane & 7);
        int ch  = 2 * ks + (lane >> 4);
        ldsm_x4(qf[ks], sb + 32768 + SW(row, ch));
    }
    __syncthreads();                     // Q reads done; ring2 reclaimed
    if (ktbeg + 1 <= ktend) issue_kv(ktbeg + 1, 1);

    float O[8][4];
    #pragma unroll
    for (int i = 0; i < 8; i++)
        #pragma unroll
        for (int r = 0; r < 4; r++) O[i][r] = 0.f;
    float l0r = 0.f, l1r = 0.f;

    const int gr = lane >> 2;
    const int gc = 2 * (lane & 3);
    const int r0 = wq * 16 + gr;
    const int r1 = r0 + 8;
    const int grow0 = q0 + r0;
    const int grow1 = q0 + r1;

    for (int kt = ktbeg; kt <= ktend; kt++) {
        const int idx = kt - ktbeg;
        const int buf = idx % 3;
        if (kt + 1 <= ktend) { CP_WAIT(1); } else { CP_WAIT(0); }
        __syncthreads();                 // all warps past reads of (idx+2)%3
        if (kt + 2 <= ktend) issue_kv(kt + 2, (idx + 2) % 3);

        const uint32_t KB = sb + buf * 16384;
        const uint32_t VB = KB + 8192;

        float S[8][4];
        #pragma unroll
        for (int i = 0; i < 8; i++)
            #pragma unroll
            for (int r = 0; r < 4; r++) S[i][r] = -MAXLOG;

        #pragma unroll
        for (int ks = 0; ks < 4; ks++) {
            uint32_t bh[4][4];
            #pragma unroll
            for (int np = 0; np < 4; np++) {
                int row = np * 16 + ((lane >> 4) << 3) + (lane & 7);
                int ch  = 2 * ks + ((lane >> 3) & 1);
                ldsm_x4(bh[np], KB + SW(row, ch));
            }
            #pragma unroll
            for (int nf = 0; nf < 8; nf++)
                mma16816h(S[nf], qf[ks], &bh[nf >> 1][(nf & 1) * 2]);
        }

        if (kt >= 2 * qt) {
            const int k0c = kt * 64;
            #pragma unroll
            for (int nf = 0; nf < 8; nf++) {
                int cg = k0c + 8 * nf + gc;
                if (cg     > grow0) S[nf][0] = -1e30f;
                if (cg + 1 > grow0) S[nf][1] = -1e30f;
                if (cg     > grow1) S[nf][2] = -1e30f;
                if (cg + 1 > grow1) S[nf][3] = -1e30f;
            }
        }

        // p = ex2(S - MAXLOG) (bias pre-seeded in accumulator init); PV per js
        #pragma unroll
        for (int js = 0; js < 4; js++) {
            uint32_t Ap[4];
            #pragma unroll
            for (int half = 0; half < 2; half++) {
                const int nf = 2 * js + half;
                float p0 = ex2(S[nf][0]);
                float p1 = ex2(S[nf][1]);
                float p2 = ex2(S[nf][2]);
                float p3 = ex2(S[nf][3]);
                l0r += p0 + p1;
                l1r += p2 + p3;
                Ap[half * 2 + 0] = pack_half2(p0, p1);
                Ap[half * 2 + 1] = pack_half2(p2, p3);
            }
            uint32_t vh[4][4];
            #pragma unroll
            for (int np = 0; np < 4; np++) {
                int row = js * 16 + ((lane >> 3) & 1) * 8 + (lane & 7);
                int ch  = 2 * np + (lane >> 4);
                ldsm_x4_t(vh[np], VB + SW(row, ch));
            }
            #pragma unroll
            for (int nf = 0; nf < 8; nf++)
                mma16816h(O[nf], Ap, &vh[nf >> 1][(nf & 1) * 2]);
        }
    }

    // final l reduction across the 4 lanes of each row group
    l0r += __shfl_xor_sync(0xffffffffu, l0r, 1);
    l0r += __shfl_xor_sync(0xffffffffu, l0r, 2);
    l1r += __shfl_xor_sync(0xffffffffu, l1r, 1);
    l1r += __shfl_xor_sync(0xffffffffu, l1r, 2);

    // epilogue: unnormalized partial O (fp32, scale 2^-12) + l per row
    float* part = g_part + (size_t)z * T_SEQ * DMODEL;
    #pragma unroll
    for (int nf = 0; nf < 8; nf++) {
        const size_t col = hcol + 8 * nf + gc;
        *(float2*)&part[(size_t)grow0 * DMODEL + col] =
            make_float2(O[nf][0], O[nf][1]);
        *(float2*)&part[(size_t)grow1 * DMODEL + col] =
            make_float2(O[nf][2], O[nf][3]);
    }
    if ((lane & 3) == 0) {
        float* lp = g_l + (size_t)z * T_SEQ * NHEADS;
        lp[grow0 * NHEADS + h] = l0r;
        lp[grow1 * NHEADS + h] = l1r;
    }
}

// ---------------------------------------------------------------------------
// Combine the two split-K halves: y = (O0 + O1) / (l0 + l1).
// ---------------------------------------------------------------------------
extern "C" __global__ void __launch_bounds__(256)
combine_attn()
{
    const int t = blockIdx.x;
    const int c0 = threadIdx.x * 4;          // 4 cols per thread
    const int h = c0 >> 6;

    const float l0 = g_l[(size_t)t * NHEADS + h];
    const float l1 = g_l[(size_t)(T_SEQ + t) * NHEADS + h];
    const float inv = 1.f / (l0 + l1);

    const size_t idx = (size_t)t * DMODEL + c0;
    float4 p0 = *(const float4*)&g_part[idx];
    float4 p1 = *(const float4*)&g_part[(size_t)T_SEQ * DMODEL + idx];
    uint2 o;
    o.x = pack_half2((p0.x + p1.x) * inv, (p0.y + p1.y) * inv);
    o.y = pack_half2((p0.z + p1.z) * inv, (p0.w + p1.w) * inv);
    *(uint2*)(g_y16 + idx) = o;
}

// ---------------------------------------------------------------------------
extern "C" void kernel_launch(void* const* d_in, const int* in_sizes, int n_in,
                              void* d_out, int out_size)
{
    const float* x   = (const float*)d_in[0];
    const float* vi  = (const float*)d_in[1];
    const float* Wq  = (const float*)d_in[2];
    const float* Wk  = (const float*)d_in[3];
    const float* Wv  = (const float*)d_in[4];
    const float* Wp  = (const float*)d_in[5];
    const float* lam = (const float*)d_in[6];
    float* out = (float*)d_out;

    float *gq, *gk, *gv;
    __half *gx16, *gy16, *gWqkv16, *gWp16;
    cudaGetSymbolAddress((void**)&gq, g_q);
    cudaGetSymbolAddress((void**)&gk, g_k);
    cudaGetSymbolAddress((void**)&gv, g_v);
    cudaGetSymbolAddress((void**)&gx16, g_x16);
    cudaGetSymbolAddress((void**)&gy16, g_y16);
    cudaGetSymbolAddress((void**)&gWqkv16, g_Wqkv16);
    cudaGetSymbolAddress((void**)&gWp16, g_Wp16);

    cudaFuncSetAttribute(gemm_f16, cudaFuncAttributeMaxDynamicSharedMemorySize,
                         GEMM_SMEM_BYTES);
    cudaFuncSetAttribute(flash_mma, cudaFuncAttributeMaxDynamicSharedMemorySize,
                         FLASH_SMEM_BYTES);

    pack16<<<dim3(256, 5), 256>>>(x, Wq, Wk, Wv, Wp);

    // fused QKV: N = 3072
    gemm_f16<<<dim3(3 * DMODEL / 128, T_SEQ / 128), 256, GEMM_SMEM_BYTES>>>(
        gx16, gWqkv16, gq, gk, gv);

    qkv_post<<<T_SEQ * NHEADS / 8, 256>>>(vi, lam);

    flash_mma<<<dim3(T_SEQ / 128, NHEADS, 2), 256, FLASH_SMEM_BYTES>>>();
    combine_attn<<<T_SEQ, 256>>>();

    gemm_f16<<<dim3(DMODEL / 128, T_SEQ / 128), 256, GEMM_SMEM_BYTES>>>(
        gy16, gWp16, out, out, out);
}

// round 13
// speedup vs baseline: 1.4813x; 1.4813x over previous
#include <cuda_runtime.h>
#include <cuda_bf16.h>
#include <cuda_fp16.h>
#include <math.h>
#include <stdint.h>

#define T_SEQ  2048
#define DMODEL 1024
#define NHEADS 16
#define HDIM   64
#define KDIM   1024
#define BK     64
#define NSTAGES (KDIM / BK)      // 16
#define NPIPE  3
#define NSPLIT 4

// ---------------------------------------------------------------------------
// Scratch (static device globals — no allocation allowed in kernel_launch)
// ---------------------------------------------------------------------------
__device__ float g_q[T_SEQ * DMODEL];
__device__ float g_k[T_SEQ * DMODEL];
__device__ float g_v[T_SEQ * DMODEL];
__device__ __align__(16) __half g_x16[T_SEQ * DMODEL];
__device__ __align__(16) __half g_y16[T_SEQ * DMODEL];
__device__ __align__(16) __half g_Wqkv16[3 * DMODEL * DMODEL];
__device__ __align__(16) __half g_Wp16[DMODEL * DMODEL];
// fp16 q/k/v for attention (q pre-scaled by 0.125*log2e)
__device__ __align__(16) __half g_q16[T_SEQ * DMODEL];
__device__ __align__(16) __half g_k16[T_SEQ * DMODEL];
__device__ __align__(16) __half g_v16[T_SEQ * DMODEL];
// split-K attention partials (uniformly scaled by 2^-12; cancels in combine)
__device__ __align__(16) float g_part[NSPLIT * T_SEQ * DMODEL];
__device__ float g_l[NSPLIT * T_SEQ * NHEADS];   // [z][t][h] row sums

// ---------------------------------------------------------------------------
__device__ __forceinline__ uint32_t smem_u32(const void* p) {
    uint32_t a;
    asm("{ .reg .u64 t; cvta.to.shared.u64 t, %1; cvt.u32.u64 %0, t; }"
        : "=r"(a) : "l"(p));
    return a;
}

__device__ __forceinline__ void ldsm_x4(uint32_t* r, uint32_t addr) {
    asm volatile("ldmatrix.sync.aligned.m8n8.x4.shared.b16 {%0,%1,%2,%3}, [%4];"
                 : "=r"(r[0]), "=r"(r[1]), "=r"(r[2]), "=r"(r[3]) : "r"(addr));
}

__device__ __forceinline__ void ldsm_x4_t(uint32_t* r, uint32_t addr) {
    asm volatile("ldmatrix.sync.aligned.m8n8.x4.trans.shared.b16 {%0,%1,%2,%3}, [%4];"
                 : "=r"(r[0]), "=r"(r[1]), "=r"(r[2]), "=r"(r[3]) : "r"(addr));
}

// fp16 MMA, fp32 accumulate
__device__ __forceinline__ void mma16816h(float* d, const uint32_t* a,
                                          const uint32_t* b) {
    asm volatile(
        "mma.sync.aligned.m16n8k16.row.col.f32.f16.f16.f32 "
        "{%0,%1,%2,%3}, {%4,%5,%6,%7}, {%8,%9}, {%0,%1,%2,%3};"
        : "+f"(d[0]), "+f"(d[1]), "+f"(d[2]), "+f"(d[3])
        : "r"(a[0]), "r"(a[1]), "r"(a[2]), "r"(a[3]), "r"(b[0]), "r"(b[1]));
}

__device__ __forceinline__ uint32_t pack_half2(float lo, float hi) {
    uint32_t r;
    asm("cvt.rn.f16x2.f32 %0, %1, %2;" : "=r"(r) : "f"(hi), "f"(lo));
    return r;
}

__device__ __forceinline__ float ex2(float x) {
    float r;
    asm("ex2.approx.f32 %0, %1;" : "=f"(r) : "f"(x));
    return r;
}

__device__ __forceinline__ void cp_async16(uint32_t dst, const void* src) {
    asm volatile("cp.async.cg.shared.global [%0], [%1], 16;"
                 :: "r"(dst), "l"(src));
}
#define CP_COMMIT() asm volatile("cp.async.commit_group;" ::: "memory")
#define CP_WAIT(n)  asm volatile("cp.async.wait_group %0;" :: "n"(n) : "memory")

// ---------------------------------------------------------------------------
// fp32 -> fp16 conversion: y selects among {x, Wq, Wk, Wv, Wp}
// ---------------------------------------------------------------------------
extern "C" __global__ void pack16(const float* __restrict__ x,
                                  const float* __restrict__ wq,
                                  const float* __restrict__ wk,
                                  const float* __restrict__ wv,
                                  const float* __restrict__ wp)
{
    const int y = blockIdx.y;
    const float* s;
    __half* d;
    int n4;
    if (y == 0)      { s = x;  d = g_x16;                          n4 = T_SEQ * DMODEL / 4; }
    else if (y == 1) { s = wq; d = g_Wqkv16;                       n4 = DMODEL * DMODEL / 4; }
    else if (y == 2) { s = wk; d = g_Wqkv16 + DMODEL * DMODEL;     n4 = DMODEL * DMODEL / 4; }
    else if (y == 3) { s = wv; d = g_Wqkv16 + 2 * DMODEL * DMODEL; n4 = DMODEL * DMODEL / 4; }
    else             { s = wp; d = g_Wp16;                         n4 = DMODEL * DMODEL / 4; }

    for (int i = blockIdx.x * blockDim.x + threadIdx.x; i < n4;
         i += gridDim.x * blockDim.x) {
        float4 v = ((const float4*)s)[i];
        uint2 o;
        o.x = pack_half2(v.x, v.y);
        o.y = pack_half2(v.z, v.w);
        ((uint2*)d)[i] = o;
    }
}

// ---------------------------------------------------------------------------
// mma.sync fp16 GEMM, cp.async 3-stage pipeline, 2 CTAs/SM.
// (R11 structure: issue-before-compute, double sync per stage.)
// ---------------------------------------------------------------------------
#define GEMM_SMEM_BYTES (NPIPE * 32768)

extern "C" __global__ void __launch_bounds__(256, 2)
gemm_f16(const __half* __restrict__ A,
         const __half* __restrict__ B,
         float* __restrict__ C0, float* __restrict__ C1,
         float* __restrict__ C2)
{
    extern __shared__ __align__(1024) char smem[];
    const uint32_t sbase = smem_u32(smem);

    const int tid  = threadIdx.x;
    const int wid  = tid >> 5;
    const int lane = tid & 31;
    const int n0 = blockIdx.x * 128;
    const int m0 = blockIdx.y * 128;
    const int wm = (wid >> 2) * 64;
    const int wn = (wid & 3) * 32;

    const int lrow = tid >> 3;
    const int lq   = tid & 7;
    const __half* Ag = A + (size_t)(m0 + lrow) * KDIM + lq * 8;
    const __half* Bg = B + (size_t)(n0 + lrow) * KDIM + lq * 8;
    const uint32_t st_off = lrow * 128 + ((lq ^ (lrow & 7)) << 4);

    uint32_t aoff[4][4], boff[4][2];
    #pragma unroll
    for (int ks = 0; ks < 4; ks++) {
        #pragma unroll
        for (int mf = 0; mf < 4; mf++) {
            int row = wm + 16 * mf + ((lane >> 3) & 1) * 8 + (lane & 7);
            int ch  = 2 * ks + (lane >> 4);
            aoff[ks][mf] = row * 128 + ((ch ^ (row & 7)) << 4);
        }
        #pragma unroll
        for (int np = 0; np < 2; np++) {
            int row = wn + 16 * np + ((lane >> 4) << 3) + (lane & 7);
            int ch  = 2 * ks + ((lane >> 3) & 1);
            boff[ks][np] = row * 128 + ((ch ^ (row & 7)) << 4);
        }
    }

    float acc[4][4][4];
    #pragma unroll
    for (int i = 0; i < 4; i++)
        #pragma unroll
        for (int j = 0; j < 4; j++)
            #pragma unroll
            for (int r = 0; r < 4; r++) acc[i][j][r] = 0.f;

    auto issue = [&](int s) {
        const uint32_t dst = sbase + (s % NPIPE) * 32768 + st_off;
        const size_t ko = (size_t)s * BK;
        #pragma unroll
        for (int j = 0; j < 4; j++) {
            cp_async16(dst + j * 4096,         Ag + (size_t)32 * j * KDIM + ko);
            cp_async16(dst + 16384 + j * 4096, Bg + (size_t)32 * j * KDIM + ko);
        }
        CP_COMMIT();
    };

    #pragma unroll
    for (int s = 0; s < NPIPE - 1; s++) issue(s);

    for (int s = 0; s < NSTAGES; s++) {
        if (s + 1 < NSTAGES) { CP_WAIT(NPIPE - 2); } else { CP_WAIT(0); }
        __syncthreads();
        if (s + NPIPE - 1 < NSTAGES) issue(s + NPIPE - 1);

        const uint32_t ab32 = sbase + (s % NPIPE) * 32768;
        const uint32_t bb32 = ab32 + 16384;
        #pragma unroll
        for (int ks = 0; ks < 4; ks++) {
            uint32_t af[4][4], bf[2][4];
            #pragma unroll
            for (int mf = 0; mf < 4; mf++)
                ldsm_x4(af[mf], ab32 + aoff[ks][mf]);
            #pragma unroll
            for (int np = 0; np < 2; np++)
                ldsm_x4(bf[np], bb32 + boff[ks][np]);
            #pragma unroll
            for (int mf = 0; mf < 4; mf++)
                #pragma unroll
                for (int nf = 0; nf < 4; nf++)
                    mma16816h(acc[mf][nf], af[mf], &bf[nf >> 1][(nf & 1) * 2]);
        }
        __syncthreads();
    }

    const int sel = n0 >> 10;
    float* __restrict__ C = (sel == 0) ? C0 : (sel == 1) ? C1 : C2;
    const int nl = n0 & 1023;
    const int gr = lane >> 2;
    const int gc = (lane & 3) * 2;
    #pragma unroll
    for (int mf = 0; mf < 4; mf++)
        #pragma unroll
        for (int nf = 0; nf < 4; nf++) {
            const int row = m0 + wm + 16 * mf + gr;
            const int col = nl + wn + 8 * nf + gc;
            *(float2*)&C[(size_t)row * DMODEL + col] =
                make_float2(acc[mf][nf][0], acc[mf][nf][1]);
            *(float2*)&C[(size_t)(row + 8) * DMODEL + col] =
                make_float2(acc[mf][nf][2], acc[mf][nf][3]);
        }
}

// ---------------------------------------------------------------------------
// Fused post: one warp per (t,h). Lane j owns dims j and j+32.
// q is pre-scaled by 0.125 * log2(e) so attention works in exp2 domain.
// ---------------------------------------------------------------------------
extern "C" __global__ void __launch_bounds__(256)
qkv_post(const float* __restrict__ vi, const float* __restrict__ lambdas)
{
    const int u = blockIdx.x * 8 + (threadIdx.x >> 5);   // unit = t*16+h
    const int j = threadIdx.x & 31;
    const int t = u >> 4;
    const int h = u & 15;
    const int base = t * DMODEL + h * HDIM;
    const int i0 = base + j;
    const int i1 = base + j + 32;

    const float l0 = lambdas[0], l1 = lambdas[1];
    {
        float v0 = fmaf(l0, g_v[i0], l1 * vi[i0]);
        float v1 = fmaf(l0, g_v[i1], l1 * vi[i1]);
        g_v16[i0] = __float2half(v0);
        g_v16[i1] = __float2half(v1);
    }

    float q0 = g_q[i0], q1 = g_q[i1];
    float k0 = g_k[i0], k1 = g_k[i1];
    float qs = q0 * q0 + q1 * q1;
    float ks = k0 * k0 + k1 * k1;
    #pragma unroll
    for (int o = 16; o > 0; o >>= 1) {
        qs += __shfl_xor_sync(0xffffffffu, qs, o);
        ks += __shfl_xor_sync(0xffffffffu, ks, o);
    }
    const float eps = 1.1920929e-7f;
    const float rq = rsqrtf(qs * (1.f / 64.f) + eps);
    const float rk = rsqrtf(ks * (1.f / 64.f) + eps);
    q0 *= rq; q1 *= rq; k0 *= rk; k1 *= rk;

    float c = 1.f, s = 0.f;
    if (j < 16) {
        float invf = exp2f(-10.0f * (float)j * (1.0f / 15.0f));
        sincosf((float)t * invf, &s, &c);
    }
    const float QSC = 0.125f * 1.44269504f;   // 1/sqrt(hd) * log2(e)
    float qa = (q0 * c + q1 * s) * QSC;
    float qb = (q1 * c - q0 * s) * QSC;
    float ka =  k0 * c + k1 * s;
    float kb =  k1 * c - k0 * s;

    g_q16[i0] = __float2half(qa);
    g_q16[i1] = __float2half(qb);
    g_k16[i0] = __float2half(ka);
    g_k16[i1] = __float2half(kb);
}

// ---------------------------------------------------------------------------
// 4-way split-K fp16 flash attention, causal, exp2 domain, fixed max (12).
// R11 pipeline structure (2-buffer ring, double sync per tile).
// Grid (16 qtiles, 16 heads, 4 splits): z covers K-tiles
// [z*n/4, (z+1)*n/4) of n = 2qt+2. Empty ranges emit zero partials.
// ---------------------------------------------------------------------------
#define SW(row, q) ((row) * 128 + (((q) ^ ((row) & 7)) << 4))
#define FLASH_SMEM_BYTES (49152)
#define MAXLOG 12.0f

extern "C" __global__ void __launch_bounds__(256, 2)
flash_mma()
{
    extern __shared__ __align__(1024) char smd[];
    const uint32_t sb = smem_u32(smd);

    const int qt   = (int)gridDim.x - 1 - (int)blockIdx.x;  // heavy first
    const int h    = blockIdx.y;
    const int z    = blockIdx.z;
    const int tid  = threadIdx.x;
    const int lane = tid & 31;
    const int wq   = tid >> 5;
    const int q0   = qt * 128;
    const int n    = 2 * qt + 2;
    const int ktbeg = (z * n) >> 2;
    const int ktend = (((z + 1) * n) >> 2) - 1;   // inclusive
    const size_t hcol = (size_t)h * HDIM;

    const int gr = lane >> 2;
    const int gc = 2 * (lane & 3);
    const int r0 = wq * 16 + gr;
    const int r1 = r0 + 8;
    const int grow0 = q0 + r0;
    const int grow1 = q0 + r1;

    float O[8][4];
    #pragma unroll
    for (int i = 0; i < 8; i++)
        #pragma unroll
        for (int r = 0; r < 4; r++) O[i][r] = 0.f;
    float l0r = 0.f, l1r = 0.f;

    if (ktbeg <= ktend) {
        const int krow = tid >> 2;            // 0..63
        const int kq2  = (tid & 3) * 2;       // 0,2,4,6
        auto issue_kv = [&](int kt, int buf) {
            const uint32_t dst = sb + buf * 16384;
            const size_t gb = (size_t)(kt * 64 + krow) * DMODEL + hcol + kq2 * 8;
            #pragma unroll
            for (int j = 0; j < 2; j++) {
                const uint32_t so = SW(krow, kq2 + j);
                const size_t go = gb + (size_t)j * 8;
                cp_async16(dst + so,        g_k16 + go);
                cp_async16(dst + 8192 + so, g_v16 + go);
            }
            CP_COMMIT();
        };

        issue_kv(ktbeg, 0);
        {
            const int qrow = tid >> 1;
            const int qqb  = (tid & 1) * 4;
            const uint32_t dst = sb + 32768;
            const size_t gb = (size_t)(q0 + qrow) * DMODEL + hcol + qqb * 8;
            #pragma unroll
            for (int j = 0; j < 4; j++)
                cp_async16(dst + SW(qrow, qqb + j), g_q16 + gb + (size_t)j * 8);
            CP_COMMIT();
        }
        CP_WAIT(0);
        __syncthreads();

        uint32_t qf[4][4];
        #pragma unroll
        for (int ks = 0; ks < 4; ks++) {
            int row = wq * 16 + ((lane >> 3) & 1) * 8 + (lane & 7);
            int ch  = 2 * ks + (lane >> 4);
            ldsm_x4(qf[ks], sb + 32768 + SW(row, ch));
        }
        __syncthreads();

        for (int kt = ktbeg; kt <= ktend; kt++) {
            const int buf = (kt - ktbeg) & 1;
            if (kt > ktbeg) { CP_WAIT(0); __syncthreads(); }
            if (kt + 1 <= ktend) issue_kv(kt + 1, buf ^ 1);

            const uint32_t KB = sb + buf * 16384;
            const uint32_t VB = KB + 8192;

            float S[8][4];
            #pragma unroll
            for (int i = 0; i < 8; i++)
                #pragma unroll
                for (int r = 0; r < 4; r++) S[i][r] = -MAXLOG;

            #pragma unroll
            for (int ks = 0; ks < 4; ks++) {
                uint32_t bh[4][4];
                #pragma unroll
                for (int np = 0; np < 4; np++) {
                    int row = np * 16 + ((lane >> 4) << 3) + (lane & 7);
                    int ch  = 2 * ks + ((lane >> 3) & 1);
                    ldsm_x4(bh[np], KB + SW(row, ch));
                }
                #pragma unroll
                for (int nf = 0; nf < 8; nf++)
                    mma16816h(S[nf], qf[ks], &bh[nf >> 1][(nf & 1) * 2]);
            }

            if (kt >= 2 * qt) {
                const int k0c = kt * 64;
                #pragma unroll
                for (int nf = 0; nf < 8; nf++) {
                    int cg = k0c + 8 * nf + gc;
                    if (cg     > grow0) S[nf][0] = -1e30f;
                    if (cg + 1 > grow0) S[nf][1] = -1e30f;
                    if (cg     > grow1) S[nf][2] = -1e30f;
                    if (cg + 1 > grow1) S[nf][3] = -1e30f;
                }
            }

            // p = ex2(S - MAXLOG) (bias pre-seeded); exps + PV per js
            #pragma unroll
            for (int js = 0; js < 4; js++) {
                uint32_t Ap[4];
                #pragma unroll
                for (int half = 0; half < 2; half++) {
                    const int nf = 2 * js + half;
                    float p0 = ex2(S[nf][0]);
                    float p1 = ex2(S[nf][1]);
                    float p2 = ex2(S[nf][2]);
                    float p3 = ex2(S[nf][3]);
                    l0r += p0 + p1;
                    l1r += p2 + p3;
                    Ap[half * 2 + 0] = pack_half2(p0, p1);
                    Ap[half * 2 + 1] = pack_half2(p2, p3);
                }
                uint32_t vh[4][4];
                #pragma unroll
                for (int np = 0; np < 4; np++) {
                    int row = js * 16 + ((lane >> 3) & 1) * 8 + (lane & 7);
                    int ch  = 2 * np + (lane >> 4);
                    ldsm_x4_t(vh[np], VB + SW(row, ch));
                }
                #pragma unroll
                for (int nf = 0; nf < 8; nf++)
                    mma16816h(O[nf], Ap, &vh[nf >> 1][(nf & 1) * 2]);
            }
            __syncthreads();
        }

        l0r += __shfl_xor_sync(0xffffffffu, l0r, 1);
        l0r += __shfl_xor_sync(0xffffffffu, l0r, 2);
        l1r += __shfl_xor_sync(0xffffffffu, l1r, 1);
        l1r += __shfl_xor_sync(0xffffffffu, l1r, 2);
    }

    // epilogue: (possibly zero) unnormalized partial O + l per row
    float* part = g_part + (size_t)z * T_SEQ * DMODEL;
    #pragma unroll
    for (int nf = 0; nf < 8; nf++) {
        const size_t col = hcol + 8 * nf + gc;
        *(float2*)&part[(size_t)grow0 * DMODEL + col] =
            make_float2(O[nf][0], O[nf][1]);
        *(float2*)&part[(size_t)grow1 * DMODEL + col] =
            make_float2(O[nf][2], O[nf][3]);
    }
    if ((lane & 3) == 0) {
        float* lp = g_l + (size_t)z * T_SEQ * NHEADS;
        lp[grow0 * NHEADS + h] = l0r;
        lp[grow1 * NHEADS + h] = l1r;
    }
}

// ---------------------------------------------------------------------------
// Combine the four split-K quarters: y = sum(O_z) / sum(l_z).
// ---------------------------------------------------------------------------
extern "C" __global__ void __launch_bounds__(256)
combine_attn()
{
    const int t = blockIdx.x;
    const int c0 = threadIdx.x * 4;          // 4 cols per thread
    const int h = c0 >> 6;

    float lsum = 0.f;
    #pragma unroll
    for (int zz = 0; zz < NSPLIT; zz++)
        lsum += g_l[(size_t)(zz * T_SEQ + t) * NHEADS + h];
    const float inv = 1.f / lsum;

    const size_t idx = (size_t)t * DMODEL + c0;
    float4 acc = make_float4(0.f, 0.f, 0.f, 0.f);
    #pragma unroll
    for (int zz = 0; zz < NSPLIT; zz++) {
        float4 p = *(const float4*)&g_part[(size_t)zz * T_SEQ * DMODEL + idx];
        acc.x += p.x; acc.y += p.y; acc.z += p.z; acc.w += p.w;
    }
    uint2 o;
    o.x = pack_half2(acc.x * inv, acc.y * inv);
    o.y = pack_half2(acc.z * inv, acc.w * inv);
    *(uint2*)(g_y16 + idx) = o;
}

// ---------------------------------------------------------------------------
extern "C" void kernel_launch(void* const* d_in, const int* in_sizes, int n_in,
                              void* d_out, int out_size)
{
    const float* x   = (const float*)d_in[0];
    const float* vi  = (const float*)d_in[1];
    const float* Wq  = (const float*)d_in[2];
    const float* Wk  = (const float*)d_in[3];
    const float* Wv  = (const float*)d_in[4];
    const float* Wp  = (const float*)d_in[5];
    const float* lam = (const float*)d_in[6];
    float* out = (float*)d_out;

    float *gq, *gk, *gv;
    __half *gx16, *gy16, *gWqkv16, *gWp16;
    cudaGetSymbolAddress((void**)&gq, g_q);
    cudaGetSymbolAddress((void**)&gk, g_k);
    cudaGetSymbolAddress((void**)&gv, g_v);
    cudaGetSymbolAddress((void**)&gx16, g_x16);
    cudaGetSymbolAddress((void**)&gy16, g_y16);
    cudaGetSymbolAddress((void**)&gWqkv16, g_Wqkv16);
    cudaGetSymbolAddress((void**)&gWp16, g_Wp16);

    cudaFuncSetAttribute(gemm_f16, cudaFuncAttributeMaxDynamicSharedMemorySize,
                         GEMM_SMEM_BYTES);
    cudaFuncSetAttribute(flash_mma, cudaFuncAttributeMaxDynamicSharedMemorySize,
                         FLASH_SMEM_BYTES);

    pack16<<<dim3(256, 5), 256>>>(x, Wq, Wk, Wv, Wp);

    // fused QKV: N = 3072
    gemm_f16<<<dim3(3 * DMODEL / 128, T_SEQ / 128), 256, GEMM_SMEM_BYTES>>>(
        gx16, gWqkv16, gq, gk, gv);

    qkv_post<<<T_SEQ * NHEADS / 8, 256>>>(vi, lam);

    flash_mma<<<dim3(T_SEQ / 128, NHEADS, NSPLIT), 256, FLASH_SMEM_BYTES>>>();
    combine_attn<<<T_SEQ, 256>>>();

    gemm_f16<<<dim3(DMODEL / 128, T_SEQ / 128), 256, GEMM_SMEM_BYTES>>>(
        gy16, gWp16, out, out, out);
}

// round 14
// speedup vs baseline: 1.5089x; 1.0186x over previous
#include <cuda_runtime.h>
#include <cuda_bf16.h>
#include <cuda_fp16.h>
#include <math.h>
#include <stdint.h>

#define T_SEQ  2048
#define DMODEL 1024
#define NHEADS 16
#define HDIM   64
#define KDIM   1024
#define BK     64
#define NSTAGES (KDIM / BK)      // 16
#define NPIPE  3
#define NSPLIT 4

// ---------------------------------------------------------------------------
// Scratch (static device globals — no allocation allowed in kernel_launch)
// ---------------------------------------------------------------------------
__device__ __align__(16) __half g_qh[T_SEQ * DMODEL];   // raw q (GEMM out)
__device__ __align__(16) __half g_kh[T_SEQ * DMODEL];
__device__ __align__(16) __half g_vh[T_SEQ * DMODEL];
__device__ __align__(16) __half g_x16[T_SEQ * DMODEL];
__device__ __align__(16) __half g_y16[T_SEQ * DMODEL];
__device__ __align__(16) __half g_Wqkv16[3 * DMODEL * DMODEL];
__device__ __align__(16) __half g_Wp16[DMODEL * DMODEL];
// fp16 q/k/v for attention (q pre-scaled by 0.125*log2e)
__device__ __align__(16) __half g_q16[T_SEQ * DMODEL];
__device__ __align__(16) __half g_k16[T_SEQ * DMODEL];
__device__ __align__(16) __half g_v16[T_SEQ * DMODEL];
// split-K attention partials, fp16 (uniform 2^-12 scale cancels in combine)
__device__ __align__(16) __half g_part16[NSPLIT * T_SEQ * DMODEL];
__device__ float g_l[NSPLIT * T_SEQ * NHEADS];   // [z][t][h] row sums

// ---------------------------------------------------------------------------
__device__ __forceinline__ uint32_t smem_u32(const void* p) {
    uint32_t a;
    asm("{ .reg .u64 t; cvta.to.shared.u64 t, %1; cvt.u32.u64 %0, t; }"
        : "=r"(a) : "l"(p));
    return a;
}

__device__ __forceinline__ void ldsm_x4(uint32_t* r, uint32_t addr) {
    asm volatile("ldmatrix.sync.aligned.m8n8.x4.shared.b16 {%0,%1,%2,%3}, [%4];"
                 : "=r"(r[0]), "=r"(r[1]), "=r"(r[2]), "=r"(r[3]) : "r"(addr));
}

__device__ __forceinline__ void ldsm_x4_t(uint32_t* r, uint32_t addr) {
    asm volatile("ldmatrix.sync.aligned.m8n8.x4.trans.shared.b16 {%0,%1,%2,%3}, [%4];"
                 : "=r"(r[0]), "=r"(r[1]), "=r"(r[2]), "=r"(r[3]) : "r"(addr));
}

// fp16 MMA, fp32 accumulate
__device__ __forceinline__ void mma16816h(float* d, const uint32_t* a,
                                          const uint32_t* b) {
    asm volatile(
        "mma.sync.aligned.m16n8k16.row.col.f32.f16.f16.f32 "
        "{%0,%1,%2,%3}, {%4,%5,%6,%7}, {%8,%9}, {%0,%1,%2,%3};"
        : "+f"(d[0]), "+f"(d[1]), "+f"(d[2]), "+f"(d[3])
        : "r"(a[0]), "r"(a[1]), "r"(a[2]), "r"(a[3]), "r"(b[0]), "r"(b[1]));
}

__device__ __forceinline__ uint32_t pack_half2(float lo, float hi) {
    uint32_t r;
    asm("cvt.rn.f16x2.f32 %0, %1, %2;" : "=r"(r) : "f"(hi), "f"(lo));
    return r;
}

__device__ __forceinline__ float ex2(float x) {
    float r;
    asm("ex2.approx.f32 %0, %1;" : "=f"(r) : "f"(x));
    return r;
}

__device__ __forceinline__ void cp_async16(uint32_t dst, const void* src) {
    asm volatile("cp.async.cg.shared.global [%0], [%1], 16;"
                 :: "r"(dst), "l"(src));
}
#define CP_COMMIT() asm volatile("cp.async.commit_group;" ::: "memory")
#define CP_WAIT(n)  asm volatile("cp.async.wait_group %0;" :: "n"(n) : "memory")

// ---------------------------------------------------------------------------
// fp32 -> fp16 conversion: y selects among {x, Wq, Wk, Wv, Wp}
// ---------------------------------------------------------------------------
extern "C" __global__ void pack16(const float* __restrict__ x,
                                  const float* __restrict__ wq,
                                  const float* __restrict__ wk,
                                  const float* __restrict__ wv,
                                  const float* __restrict__ wp)
{
    const int y = blockIdx.y;
    const float* s;
    __half* d;
    int n4;
    if (y == 0)      { s = x;  d = g_x16;                          n4 = T_SEQ * DMODEL / 4; }
    else if (y == 1) { s = wq; d = g_Wqkv16;                       n4 = DMODEL * DMODEL / 4; }
    else if (y == 2) { s = wk; d = g_Wqkv16 + DMODEL * DMODEL;     n4 = DMODEL * DMODEL / 4; }
    else if (y == 3) { s = wv; d = g_Wqkv16 + 2 * DMODEL * DMODEL; n4 = DMODEL * DMODEL / 4; }
    else             { s = wp; d = g_Wp16;                         n4 = DMODEL * DMODEL / 4; }

    for (int i = blockIdx.x * blockDim.x + threadIdx.x; i < n4;
         i += gridDim.x * blockDim.x) {
        float4 v = ((const float4*)s)[i];
        uint2 o;
        o.x = pack_half2(v.x, v.y);
        o.y = pack_half2(v.z, v.w);
        ((uint2*)d)[i] = o;
    }
}

// ---------------------------------------------------------------------------
// mma.sync fp16 GEMM, cp.async 3-stage pipeline, 2 CTAs/SM.
// half_out=1: C buffers are __half (QKV); half_out=0: fp32 (proj -> out).
// ---------------------------------------------------------------------------
#define GEMM_SMEM_BYTES (NPIPE * 32768)

extern "C" __global__ void __launch_bounds__(256, 2)
gemm_f16(const __half* __restrict__ A,
         const __half* __restrict__ B,
         void* __restrict__ C0, void* __restrict__ C1,
         void* __restrict__ C2, int half_out)
{
    extern __shared__ __align__(1024) char smem[];
    const uint32_t sbase = smem_u32(smem);

    const int tid  = threadIdx.x;
    const int wid  = tid >> 5;
    const int lane = tid & 31;
    const int n0 = blockIdx.x * 128;
    const int m0 = blockIdx.y * 128;
    const int wm = (wid >> 2) * 64;
    const int wn = (wid & 3) * 32;

    const int lrow = tid >> 3;
    const int lq   = tid & 7;
    const __half* Ag = A + (size_t)(m0 + lrow) * KDIM + lq * 8;
    const __half* Bg = B + (size_t)(n0 + lrow) * KDIM + lq * 8;
    const uint32_t st_off = lrow * 128 + ((lq ^ (lrow & 7)) << 4);

    uint32_t aoff[4][4], boff[4][2];
    #pragma unroll
    for (int ks = 0; ks < 4; ks++) {
        #pragma unroll
        for (int mf = 0; mf < 4; mf++) {
            int row = wm + 16 * mf + ((lane >> 3) & 1) * 8 + (lane & 7);
            int ch  = 2 * ks + (lane >> 4);
            aoff[ks][mf] = row * 128 + ((ch ^ (row & 7)) << 4);
        }
        #pragma unroll
        for (int np = 0; np < 2; np++) {
            int row = wn + 16 * np + ((lane >> 4) << 3) + (lane & 7);
            int ch  = 2 * ks + ((lane >> 3) & 1);
            boff[ks][np] = row * 128 + ((ch ^ (row & 7)) << 4);
        }
    }

    float acc[4][4][4];
    #pragma unroll
    for (int i = 0; i < 4; i++)
        #pragma unroll
        for (int j = 0; j < 4; j++)
            #pragma unroll
            for (int r = 0; r < 4; r++) acc[i][j][r] = 0.f;

    auto issue = [&](int s) {
        const uint32_t dst = sbase + (s % NPIPE) * 32768 + st_off;
        const size_t ko = (size_t)s * BK;
        #pragma unroll
        for (int j = 0; j < 4; j++) {
            cp_async16(dst + j * 4096,         Ag + (size_t)32 * j * KDIM + ko);
            cp_async16(dst + 16384 + j * 4096, Bg + (size_t)32 * j * KDIM + ko);
        }
        CP_COMMIT();
    };

    #pragma unroll
    for (int s = 0; s < NPIPE - 1; s++) issue(s);

    for (int s = 0; s < NSTAGES; s++) {
        if (s + 1 < NSTAGES) { CP_WAIT(NPIPE - 2); } else { CP_WAIT(0); }
        __syncthreads();
        if (s + NPIPE - 1 < NSTAGES) issue(s + NPIPE - 1);

        const uint32_t ab32 = sbase + (s % NPIPE) * 32768;
        const uint32_t bb32 = ab32 + 16384;
        #pragma unroll
        for (int ks = 0; ks < 4; ks++) {
            uint32_t af[4][4], bf[2][4];
            #pragma unroll
            for (int mf = 0; mf < 4; mf++)
                ldsm_x4(af[mf], ab32 + aoff[ks][mf]);
            #pragma unroll
            for (int np = 0; np < 2; np++)
                ldsm_x4(bf[np], bb32 + boff[ks][np]);
            #pragma unroll
            for (int mf = 0; mf < 4; mf++)
                #pragma unroll
                for (int nf = 0; nf < 4; nf++)
                    mma16816h(acc[mf][nf], af[mf], &bf[nf >> 1][(nf & 1) * 2]);
        }
        __syncthreads();
    }

    const int sel = n0 >> 10;
    void* __restrict__ Cv = (sel == 0) ? C0 : (sel == 1) ? C1 : C2;
    const int nl = n0 & 1023;
    const int gr = lane >> 2;
    const int gc = (lane & 3) * 2;
    if (half_out) {
        __half* __restrict__ C = (__half*)Cv;
        #pragma unroll
        for (int mf = 0; mf < 4; mf++)
            #pragma unroll
            for (int nf = 0; nf < 4; nf++) {
                const int row = m0 + wm + 16 * mf + gr;
                const int col = nl + wn + 8 * nf + gc;
                *(uint32_t*)&C[(size_t)row * DMODEL + col] =
                    pack_half2(acc[mf][nf][0], acc[mf][nf][1]);
                *(uint32_t*)&C[(size_t)(row + 8) * DMODEL + col] =
                    pack_half2(acc[mf][nf][2], acc[mf][nf][3]);
            }
    } else {
        float* __restrict__ C = (float*)Cv;
        #pragma unroll
        for (int mf = 0; mf < 4; mf++)
            #pragma unroll
            for (int nf = 0; nf < 4; nf++) {
                const int row = m0 + wm + 16 * mf + gr;
                const int col = nl + wn + 8 * nf + gc;
                *(float2*)&C[(size_t)row * DMODEL + col] =
                    make_float2(acc[mf][nf][0], acc[mf][nf][1]);
                *(float2*)&C[(size_t)(row + 8) * DMODEL + col] =
                    make_float2(acc[mf][nf][2], acc[mf][nf][3]);
            }
    }
}

// ---------------------------------------------------------------------------
// Fused post: one warp per (t,h). Lane j owns dims j and j+32.
// Reads fp16 raw q/k/v; q pre-scaled by 0.125*log2(e) (exp2 domain).
// ---------------------------------------------------------------------------
extern "C" __global__ void __launch_bounds__(256)
qkv_post(const float* __restrict__ vi, const float* __restrict__ lambdas)
{
    const int u = blockIdx.x * 8 + (threadIdx.x >> 5);   // unit = t*16+h
    const int j = threadIdx.x & 31;
    const int t = u >> 4;
    const int h = u & 15;
    const int base = t * DMODEL + h * HDIM;
    const int i0 = base + j;
    const int i1 = base + j + 32;

    const float l0 = lambdas[0], l1 = lambdas[1];
    {
        float v0 = fmaf(l0, __half2float(g_vh[i0]), l1 * vi[i0]);
        float v1 = fmaf(l0, __half2float(g_vh[i1]), l1 * vi[i1]);
        g_v16[i0] = __float2half(v0);
        g_v16[i1] = __float2half(v1);
    }

    float q0 = __half2float(g_qh[i0]), q1 = __half2float(g_qh[i1]);
    float k0 = __half2float(g_kh[i0]), k1 = __half2float(g_kh[i1]);
    float qs = q0 * q0 + q1 * q1;
    float ks = k0 * k0 + k1 * k1;
    #pragma unroll
    for (int o = 16; o > 0; o >>= 1) {
        qs += __shfl_xor_sync(0xffffffffu, qs, o);
        ks += __shfl_xor_sync(0xffffffffu, ks, o);
    }
    const float eps = 1.1920929e-7f;
    const float rq = rsqrtf(qs * (1.f / 64.f) + eps);
    const float rk = rsqrtf(ks * (1.f / 64.f) + eps);
    q0 *= rq; q1 *= rq; k0 *= rk; k1 *= rk;

    float c = 1.f, s = 0.f;
    if (j < 16) {
        float invf = exp2f(-10.0f * (float)j * (1.0f / 15.0f));
        sincosf((float)t * invf, &s, &c);
    }
    const float QSC = 0.125f * 1.44269504f;   // 1/sqrt(hd) * log2(e)
    float qa = (q0 * c + q1 * s) * QSC;
    float qb = (q1 * c - q0 * s) * QSC;
    float ka =  k0 * c + k1 * s;
    float kb =  k1 * c - k0 * s;

    g_q16[i0] = __float2half(qa);
    g_q16[i1] = __float2half(qb);
    g_k16[i0] = __float2half(ka);
    g_k16[i1] = __float2half(kb);
}

// ---------------------------------------------------------------------------
// 4-way split-K fp16 flash attention, causal, exp2 domain, fixed max (12).
// 2-buffer ring, double sync per tile (R13 structure). Partials in fp16.
// ---------------------------------------------------------------------------
#define SW(row, q) ((row) * 128 + (((q) ^ ((row) & 7)) << 4))
#define FLASH_SMEM_BYTES (49152)
#define MAXLOG 12.0f

extern "C" __global__ void __launch_bounds__(256, 2)
flash_mma()
{
    extern __shared__ __align__(1024) char smd[];
    const uint32_t sb = smem_u32(smd);

    const int qt   = (int)gridDim.x - 1 - (int)blockIdx.x;  // heavy first
    const int h    = blockIdx.y;
    const int z    = blockIdx.z;
    const int tid  = threadIdx.x;
    const int lane = tid & 31;
    const int wq   = tid >> 5;
    const int q0   = qt * 128;
    const int n    = 2 * qt + 2;
    const int ktbeg = (z * n) >> 2;
    const int ktend = (((z + 1) * n) >> 2) - 1;   // inclusive
    const size_t hcol = (size_t)h * HDIM;

    const int gr = lane >> 2;
    const int gc = 2 * (lane & 3);
    const int r0 = wq * 16 + gr;
    const int r1 = r0 + 8;
    const int grow0 = q0 + r0;
    const int grow1 = q0 + r1;

    float O[8][4];
    #pragma unroll
    for (int i = 0; i < 8; i++)
        #pragma unroll
        for (int r = 0; r < 4; r++) O[i][r] = 0.f;
    float l0r = 0.f, l1r = 0.f;

    if (ktbeg <= ktend) {
        const int krow = tid >> 2;            // 0..63
        const int kq2  = (tid & 3) * 2;       // 0,2,4,6
        auto issue_kv = [&](int kt, int buf) {
            const uint32_t dst = sb + buf * 16384;
            const size_t gb = (size_t)(kt * 64 + krow) * DMODEL + hcol + kq2 * 8;
            #pragma unroll
            for (int j = 0; j < 2; j++) {
                const uint32_t so = SW(krow, kq2 + j);
                const size_t go = gb + (size_t)j * 8;
                cp_async16(dst + so,        g_k16 + go);
                cp_async16(dst + 8192 + so, g_v16 + go);
            }
            CP_COMMIT();
        };

        issue_kv(ktbeg, 0);
        {
            const int qrow = tid >> 1;
            const int qqb  = (tid & 1) * 4;
            const uint32_t dst = sb + 32768;
            const size_t gb = (size_t)(q0 + qrow) * DMODEL + hcol + qqb * 8;
            #pragma unroll
            for (int j = 0; j < 4; j++)
                cp_async16(dst + SW(qrow, qqb + j), g_q16 + gb + (size_t)j * 8);
            CP_COMMIT();
        }
        CP_WAIT(0);
        __syncthreads();

        uint32_t qf[4][4];
        #pragma unroll
        for (int ks = 0; ks < 4; ks++) {
            int row = wq * 16 + ((lane >> 3) & 1) * 8 + (lane & 7);
            int ch  = 2 * ks + (lane >> 4);
            ldsm_x4(qf[ks], sb + 32768 + SW(row, ch));
        }
        __syncthreads();

        for (int kt = ktbeg; kt <= ktend; kt++) {
            const int buf = (kt - ktbeg) & 1;
            if (kt > ktbeg) { CP_WAIT(0); __syncthreads(); }
            if (kt + 1 <= ktend) issue_kv(kt + 1, buf ^ 1);

            const uint32_t KB = sb + buf * 16384;
            const uint32_t VB = KB + 8192;

            float S[8][4];
            #pragma unroll
            for (int i = 0; i < 8; i++)
                #pragma unroll
                for (int r = 0; r < 4; r++) S[i][r] = -MAXLOG;

            #pragma unroll
            for (int ks = 0; ks < 4; ks++) {
                uint32_t bh[4][4];
                #pragma unroll
                for (int np = 0; np < 4; np++) {
                    int row = np * 16 + ((lane >> 4) << 3) + (lane & 7);
                    int ch  = 2 * ks + ((lane >> 3) & 1);
                    ldsm_x4(bh[np], KB + SW(row, ch));
                }
                #pragma unroll
                for (int nf = 0; nf < 8; nf++)
                    mma16816h(S[nf], qf[ks], &bh[nf >> 1][(nf & 1) * 2]);
            }

            if (kt >= 2 * qt) {
                const int k0c = kt * 64;
                #pragma unroll
                for (int nf = 0; nf < 8; nf++) {
                    int cg = k0c + 8 * nf + gc;
                    if (cg     > grow0) S[nf][0] = -1e30f;
                    if (cg + 1 > grow0) S[nf][1] = -1e30f;
                    if (cg     > grow1) S[nf][2] = -1e30f;
                    if (cg + 1 > grow1) S[nf][3] = -1e30f;
                }
            }

            // p = ex2(S - MAXLOG) (bias pre-seeded); exps + PV per js
            #pragma unroll
            for (int js = 0; js < 4; js++) {
                uint32_t Ap[4];
                #pragma unroll
                for (int half = 0; half < 2; half++) {
                    const int nf = 2 * js + half;
                    float p0 = ex2(S[nf][0]);
                    float p1 = ex2(S[nf][1]);
                    float p2 = ex2(S[nf][2]);
                    float p3 = ex2(S[nf][3]);
                    l0r += p0 + p1;
                    l1r += p2 + p3;
                    Ap[half * 2 + 0] = pack_half2(p0, p1);
                    Ap[half * 2 + 1] = pack_half2(p2, p3);
                }
                uint32_t vh[4][4];
                #pragma unroll
                for (int np = 0; np < 4; np++) {
                    int row = js * 16 + ((lane >> 3) & 1) * 8 + (lane & 7);
                    int ch  = 2 * np + (lane >> 4);
                    ldsm_x4_t(vh[np], VB + SW(row, ch));
                }
                #pragma unroll
                for (int nf = 0; nf < 8; nf++)
                    mma16816h(O[nf], Ap, &vh[nf >> 1][(nf & 1) * 2]);
            }
            __syncthreads();
        }

        l0r += __shfl_xor_sync(0xffffffffu, l0r, 1);
        l0r += __shfl_xor_sync(0xffffffffu, l0r, 2);
        l1r += __shfl_xor_sync(0xffffffffu, l1r, 1);
        l1r += __shfl_xor_sync(0xffffffffu, l1r, 2);
    }

    // epilogue: (possibly zero) unnormalized fp16 partial O + l per row
    __half* part = g_part16 + (size_t)z * T_SEQ * DMODEL;
    #pragma unroll
    for (int nf = 0; nf < 8; nf++) {
        const size_t col = hcol + 8 * nf + gc;
        *(uint32_t*)&part[(size_t)grow0 * DMODEL + col] =
            pack_half2(O[nf][0], O[nf][1]);
        *(uint32_t*)&part[(size_t)grow1 * DMODEL + col] =
            pack_half2(O[nf][2], O[nf][3]);
    }
    if ((lane & 3) == 0) {
        float* lp = g_l + (size_t)z * T_SEQ * NHEADS;
        lp[grow0 * NHEADS + h] = l0r;
        lp[grow1 * NHEADS + h] = l1r;
    }
}

// ---------------------------------------------------------------------------
// Combine the four split-K quarters: y = sum(O_z) / sum(l_z). fp16 partials.
// ---------------------------------------------------------------------------
extern "C" __global__ void __launch_bounds__(256)
combine_attn()
{
    const int t = blockIdx.x;
    const int c0 = threadIdx.x * 4;          // 4 cols per thread
    const int h = c0 >> 6;

    float lsum = 0.f;
    #pragma unroll
    for (int zz = 0; zz < NSPLIT; zz++)
        lsum += g_l[(size_t)(zz * T_SEQ + t) * NHEADS + h];
    const float inv = 1.f / lsum;

    const size_t idx = (size_t)t * DMODEL + c0;
    float4 acc = make_float4(0.f, 0.f, 0.f, 0.f);
    #pragma unroll
    for (int zz = 0; zz < NSPLIT; zz++) {
        const __half2* p = (const __half2*)&g_part16[(size_t)zz * T_SEQ * DMODEL + idx];
        float2 a = __half22float2(p[0]);
        float2 b = __half22float2(p[1]);
        acc.x += a.x; acc.y += a.y; acc.z += b.x; acc.w += b.y;
    }
    uint2 o;
    o.x = pack_half2(acc.x * inv, acc.y * inv);
    o.y = pack_half2(acc.z * inv, acc.w * inv);
    *(uint2*)(g_y16 + idx) = o;
}

// ---------------------------------------------------------------------------
extern "C" void kernel_launch(void* const* d_in, const int* in_sizes, int n_in,
                              void* d_out, int out_size)
{
    const float* x   = (const float*)d_in[0];
    const float* vi  = (const float*)d_in[1];
    const float* Wq  = (const float*)d_in[2];
    const float* Wk  = (const float*)d_in[3];
    const float* Wv  = (const float*)d_in[4];
    const float* Wp  = (const float*)d_in[5];
    const float* lam = (const float*)d_in[6];
    float* out = (float*)d_out;

    __half *gqh, *gkh, *gvh, *gx16, *gy16, *gWqkv16, *gWp16;
    cudaGetSymbolAddress((void**)&gqh, g_qh);
    cudaGetSymbolAddress((void**)&gkh, g_kh);
    cudaGetSymbolAddress((void**)&gvh, g_vh);
    cudaGetSymbolAddress((void**)&gx16, g_x16);
    cudaGetSymbolAddress((void**)&gy16, g_y16);
    cudaGetSymbolAddress((void**)&gWqkv16, g_Wqkv16);
    cudaGetSymbolAddress((void**)&gWp16, g_Wp16);

    cudaFuncSetAttribute(gemm_f16, cudaFuncAttributeMaxDynamicSharedMemorySize,
                         GEMM_SMEM_BYTES);
    cudaFuncSetAttribute(flash_mma, cudaFuncAttributeMaxDynamicSharedMemorySize,
                         FLASH_SMEM_BYTES);

    pack16<<<dim3(256, 5), 256>>>(x, Wq, Wk, Wv, Wp);

    // fused QKV: N = 3072, fp16 output
    gemm_f16<<<dim3(3 * DMODEL / 128, T_SEQ / 128), 256, GEMM_SMEM_BYTES>>>(
        gx16, gWqkv16, gqh, gkh, gvh, 1);

    qkv_post<<<T_SEQ * NHEADS / 8, 256>>>(vi, lam);

    flash_mma<<<dim3(T_SEQ / 128, NHEADS, NSPLIT), 256, FLASH_SMEM_BYTES>>>();
    combine_attn<<<T_SEQ, 256>>>();

    // proj: fp32 output
    gemm_f16<<<dim3(DMODEL / 128, T_SEQ / 128), 256, GEMM_SMEM_BYTES>>>(
        gy16, gWp16, out, out, out, 0);
}